// round 6
// baseline (speedup 1.0000x reference)
#include <cuda_runtime.h>

#define Bn 4096
#define P1 296            // 148 SMs x 2 blocks
#define T1 512

// Scratch. g_c1/g_c2 are accumulated via red.global and reset to zero by k2
// every launch (zero-init covers the very first run). g_rs fully rewritten.
__device__ float g_rs1[Bn];
__device__ float g_rs2[Bn];
__device__ float g_c1[Bn];
__device__ float g_c2[Bn];
__device__ float g_part[32];
__device__ unsigned g_done;                // returns to 0 every launch

__device__ __forceinline__ float ex2f(float x) {
    float r; asm("ex2.approx.ftz.f32 %0, %1;" : "=f"(r) : "f"(x)); return r;
}
__device__ __forceinline__ void redadd(float* p, float v) {
    asm volatile("red.global.add.f32 [%0], %1;" :: "l"(p), "f"(v) : "memory");
}
#define SCALE 2.8853900817779268f          // (1/t)/ln2, t = 0.5

// Pass 1: identical streaming body to the 19us version (do not disturb the
// reg allocation!), but column partials go out as 16 REDs/thread instead of
// a 9.7MB partial array.
__global__ void __launch_bounds__(T1, 2) k1_sums(const float* __restrict__ L) {
    const int t = threadIdx.x;
    const int bid = blockIdx.x;
    const int warp = t >> 5, lane = t & 31;
    const int R = (bid < 248) ? 14 : 13;   // 248*14 + 48*13 = 4096

    float c1[8], c2[8];
#pragma unroll
    for (int j = 0; j < 8; j++) { c1[j] = 0.f; c2[j] = 0.f; }

    __shared__ float s1[16][14];
    __shared__ float s2[16][14];

    int k = 0;
    for (; k + 2 <= R; k += 2) {
        const float4* __restrict__ rowA = (const float4*)(L + (size_t)(bid + k * P1) * Bn);
        const float4* __restrict__ rowB = (const float4*)(L + (size_t)(bid + (k + 1) * P1) * Bn);
        float4 a0 = __ldcs(rowA + t);
        float4 a1 = __ldcs(rowA + t + T1);
        float4 b0 = __ldcs(rowB + t);
        float4 b1 = __ldcs(rowB + t + T1);
        float xa[8] = {a0.x, a0.y, a0.z, a0.w, a1.x, a1.y, a1.z, a1.w};
        float xb[8] = {b0.x, b0.y, b0.z, b0.w, b1.x, b1.y, b1.z, b1.w};
        float ra1 = 0.f, ra2 = 0.f, rb1 = 0.f, rb2 = 0.f;
#pragma unroll
        for (int j = 0; j < 8; j++) {
            float ea = ex2f(xa[j] * SCALE);
            float eb = ex2f(xb[j] * SCALE);
            ra1 += ea;  rb1 += eb;
            c1[j] += ea + eb;
            ra2 = fmaf(ea, ea, ra2);
            rb2 = fmaf(eb, eb, rb2);
            c2[j] = fmaf(ea, ea, fmaf(eb, eb, c2[j]));
        }
#pragma unroll
        for (int o = 16; o > 0; o >>= 1) {
            ra1 += __shfl_xor_sync(~0u, ra1, o);
            ra2 += __shfl_xor_sync(~0u, ra2, o);
            rb1 += __shfl_xor_sync(~0u, rb1, o);
            rb2 += __shfl_xor_sync(~0u, rb2, o);
        }
        if (lane == 0) {
            s1[warp][k] = ra1;      s2[warp][k] = ra2;
            s1[warp][k + 1] = rb1;  s2[warp][k + 1] = rb2;
        }
    }
    if (k < R) {
        const float4* __restrict__ row = (const float4*)(L + (size_t)(bid + k * P1) * Bn);
        float4 a0 = __ldcs(row + t);
        float4 a1 = __ldcs(row + t + T1);
        float x[8] = {a0.x, a0.y, a0.z, a0.w, a1.x, a1.y, a1.z, a1.w};
        float ra1 = 0.f, ra2 = 0.f;
#pragma unroll
        for (int j = 0; j < 8; j++) {
            float e = ex2f(x[j] * SCALE);
            ra1 += e; c1[j] += e;
            ra2 = fmaf(e, e, ra2);
            c2[j] = fmaf(e, e, c2[j]);
        }
#pragma unroll
        for (int o = 16; o > 0; o >>= 1) {
            ra1 += __shfl_xor_sync(~0u, ra1, o);
            ra2 += __shfl_xor_sync(~0u, ra2, o);
        }
        if (lane == 0) { s1[warp][k] = ra1; s2[warp][k] = ra2; }
    }
    __syncthreads();
    if (t < R) {
        float a = 0.f, b = 0.f;
#pragma unroll
        for (int w = 0; w < 16; w++) { a += s1[w][t]; b += s2[w][t]; }
        g_rs1[bid + t * P1] = a;
        g_rs2[bid + t * P1] = b;
    }
    // column accumulation: cols 4t..4t+3 (j<4) and 2048+4t..+3 (j>=4)
#pragma unroll
    for (int j = 0; j < 4; j++) {
        redadd(&g_c1[4 * t + j], c1[j]);
        redadd(&g_c2[4 * t + j], c2[j]);
        redadd(&g_c1[2048 + 4 * t + j], c1[4 + j]);
        redadd(&g_c2[2048 + 4 * t + j], c2[4 + j]);
    }
}

// Pass 2: per-row loss directly from the fully-reduced sums (32KB), then
// last-block final mean. Resets g_c1/g_c2/g_done for the next replay.
__global__ void __launch_bounds__(128) k2_finalize(const float* __restrict__ L,
                                                   float* __restrict__ out) {
    const int i = blockIdx.x * 128 + threadIdx.x;   // 32 blocks x 128
    const int t = threadIdx.x;

    float rc1 = g_c1[i];
    float rc2 = g_c2[i];
    g_c1[i] = 0.0f;                                  // replay-clean
    g_c2[i] = 0.0f;

    const float Nf    = 8190.0f;                         // 2B-2
    const float minNg = 8190.0f * 0.13533528323661270f;  // N*exp(-1/t)
    float d  = L[(size_t)i * Bn + i];
    float e  = ex2f(d * SCALE);
    float e2 = e * e;
    float S1 = g_rs1[i] + rc1 - 2.0f * e;
    float S2 = g_rs2[i] + rc2 - 2.0f * e2;
    float Ng = (Nf * S2 / S1 - 0.1f * Nf * e) * (1.0f / 0.9f);
    Ng = fmaxf(Ng, minNg);
    float loss = logf((e + Ng + 1e-8f) / e);

#pragma unroll
    for (int o = 16; o > 0; o >>= 1)
        loss += __shfl_xor_sync(~0u, loss, o);
    __shared__ float s[4];
    if ((t & 31) == 0) s[t >> 5] = loss;
    __syncthreads();
    if (t == 0) g_part[blockIdx.x] = s[0] + s[1] + s[2] + s[3];

    // last arriving block computes the final fixed-order sum
    __shared__ bool last;
    if (t == 0) {
        __threadfence();
        unsigned n = atomicAdd(&g_done, 1u);
        last = (n == 31u);
    }
    __syncthreads();
    if (last && t < 32) {
        __threadfence();
        float v = __ldcg(&g_part[t]);
#pragma unroll
        for (int o = 16; o > 0; o >>= 1)
            v += __shfl_xor_sync(~0u, v, o);
        if (t == 0) {
            out[0] = v / (float)Bn;
            atomicExch(&g_done, 0u);                 // replay-clean
        }
    }
}

extern "C" void kernel_launch(void* const* d_in, const int* in_sizes, int n_in,
                              void* d_out, int out_size) {
    const float* L = (const float*)d_in[0];
    float* out = (float*)d_out;
    k1_sums<<<P1, T1>>>(L);
    k2_finalize<<<32, 128>>>(L, out);
}

// round 7
// speedup vs baseline: 1.2526x; 1.2526x over previous
#include <cuda_runtime.h>

#define Bn 4096
#define P1 444            // 148 SMs x 3 blocks (all co-resident, 48 warps/SM)
#define T1 512

// Scratch (fully rewritten every launch; g_done returns to 0 every launch)
__device__ float g_rs1[Bn];
__device__ float g_rs2[Bn];
__device__ float g_cp1[(size_t)P1 * Bn];   // 7.27 MB col partials of E
__device__ float g_cp2[(size_t)P1 * Bn];   // 7.27 MB col partials of E^2
__device__ float g_part[128];
__device__ unsigned g_done;

__device__ __forceinline__ float ex2f(float x) {
    float r; asm("ex2.approx.ftz.f32 %0, %1;" : "=f"(r) : "f"(x)); return r;
}
#define SCALE 2.8853900817779268f          // (1/t)/ln2, t = 0.5

// Pass 1: rows r = bid + k*P1 (10 rows for bid<100, else 9).
// 3 blocks/SM -> 48 warps/SM to hide DRAM latency.
__global__ void __launch_bounds__(T1, 3) k1_sums(const float* __restrict__ L) {
    const int t = threadIdx.x;
    const int bid = blockIdx.x;
    const int warp = t >> 5, lane = t & 31;
    const int R = (bid < 100) ? 10 : 9;    // 100*10 + 344*9 = 4096

    float c1[8], c2[8];
#pragma unroll
    for (int j = 0; j < 8; j++) { c1[j] = 0.f; c2[j] = 0.f; }

    __shared__ float s1[16][10];
    __shared__ float s2[16][10];

    int k = 0;
    for (; k + 2 <= R; k += 2) {
        const float4* __restrict__ rowA = (const float4*)(L + (size_t)(bid + k * P1) * Bn);
        const float4* __restrict__ rowB = (const float4*)(L + (size_t)(bid + (k + 1) * P1) * Bn);
        float4 a0 = __ldcs(rowA + t);
        float4 a1 = __ldcs(rowA + t + T1);
        float4 b0 = __ldcs(rowB + t);
        float4 b1 = __ldcs(rowB + t + T1);
        float xa[8] = {a0.x, a0.y, a0.z, a0.w, a1.x, a1.y, a1.z, a1.w};
        float xb[8] = {b0.x, b0.y, b0.z, b0.w, b1.x, b1.y, b1.z, b1.w};
        float ra1 = 0.f, ra2 = 0.f, rb1 = 0.f, rb2 = 0.f;
#pragma unroll
        for (int j = 0; j < 8; j++) {
            float ea = ex2f(xa[j] * SCALE);
            float eb = ex2f(xb[j] * SCALE);
            ra1 += ea;  rb1 += eb;
            c1[j] += ea + eb;
            ra2 = fmaf(ea, ea, ra2);
            rb2 = fmaf(eb, eb, rb2);
            c2[j] = fmaf(ea, ea, fmaf(eb, eb, c2[j]));
        }
#pragma unroll
        for (int o = 16; o > 0; o >>= 1) {
            ra1 += __shfl_xor_sync(~0u, ra1, o);
            ra2 += __shfl_xor_sync(~0u, ra2, o);
            rb1 += __shfl_xor_sync(~0u, rb1, o);
            rb2 += __shfl_xor_sync(~0u, rb2, o);
        }
        if (lane == 0) {
            s1[warp][k] = ra1;      s2[warp][k] = ra2;
            s1[warp][k + 1] = rb1;  s2[warp][k + 1] = rb2;
        }
    }
    if (k < R) {
        const float4* __restrict__ row = (const float4*)(L + (size_t)(bid + k * P1) * Bn);
        float4 a0 = __ldcs(row + t);
        float4 a1 = __ldcs(row + t + T1);
        float x[8] = {a0.x, a0.y, a0.z, a0.w, a1.x, a1.y, a1.z, a1.w};
        float ra1 = 0.f, ra2 = 0.f;
#pragma unroll
        for (int j = 0; j < 8; j++) {
            float e = ex2f(x[j] * SCALE);
            ra1 += e; c1[j] += e;
            ra2 = fmaf(e, e, ra2);
            c2[j] = fmaf(e, e, c2[j]);
        }
#pragma unroll
        for (int o = 16; o > 0; o >>= 1) {
            ra1 += __shfl_xor_sync(~0u, ra1, o);
            ra2 += __shfl_xor_sync(~0u, ra2, o);
        }
        if (lane == 0) { s1[warp][k] = ra1; s2[warp][k] = ra2; }
    }
    __syncthreads();
    if (t < R) {
        float a = 0.f, b = 0.f;
#pragma unroll
        for (int w = 0; w < 16; w++) { a += s1[w][t]; b += s2[w][t]; }
        g_rs1[bid + t * P1] = a;
        g_rs2[bid + t * P1] = b;
    }
    float4* __restrict__ p1 = (float4*)(g_cp1 + (size_t)bid * Bn);
    float4* __restrict__ p2 = (float4*)(g_cp2 + (size_t)bid * Bn);
    p1[t]      = make_float4(c1[0], c1[1], c1[2], c1[3]);
    p1[t + T1] = make_float4(c1[4], c1[5], c1[6], c1[7]);
    p2[t]      = make_float4(c2[0], c2[1], c2[2], c2[7 - 3]);
    p2[t + T1] = make_float4(c2[4], c2[5], c2[6], c2[7]);
}

// Pass 2: 128 blocks x 1024. 32 cols/block x 32 stripe-groups over 444
// stripes (L2-hot in the real graph run), smem tree, per-row loss,
// last-block fixed-order final mean.
__global__ void __launch_bounds__(1024) k2_finalize(const float* __restrict__ L,
                                                    float* __restrict__ out) {
    const int tx = threadIdx.x & 31;
    const int g  = threadIdx.x >> 5;
    const int col = blockIdx.x * 32 + tx;

    float a = 0.0f, b = 0.0f;
    for (int p = g; p < P1; p += 32) {
        a += g_cp1[(size_t)p * Bn + col];
        b += g_cp2[(size_t)p * Bn + col];
    }
    __shared__ float sa[32][33];
    __shared__ float sb[32][33];
    sa[g][tx] = a;  sb[g][tx] = b;
    __syncthreads();

    if (threadIdx.x < 32) {
        float ra = 0.0f, rb = 0.0f;
#pragma unroll
        for (int w = 0; w < 32; w++) { ra += sa[w][tx]; rb += sb[w][tx]; }
        const int i = col;
        const float Nf    = 8190.0f;                         // 2B-2
        const float minNg = 8190.0f * 0.13533528323661270f;  // N*exp(-1/t)
        float d  = L[(size_t)i * Bn + i];
        float e  = ex2f(d * SCALE);
        float e2 = e * e;
        float S1 = g_rs1[i] + ra - 2.0f * e;
        float S2 = g_rs2[i] + rb - 2.0f * e2;
        float Ng = (Nf * S2 / S1 - 0.1f * Nf * e) * (1.0f / 0.9f);
        Ng = fmaxf(Ng, minNg);
        float loss = logf((e + Ng + 1e-8f) / e);
#pragma unroll
        for (int o = 16; o > 0; o >>= 1)
            loss += __shfl_xor_sync(~0u, loss, o);
        if (tx == 0) g_part[blockIdx.x] = loss;
    }

    __shared__ bool last;
    if (threadIdx.x == 0) {
        __threadfence();
        unsigned n = atomicAdd(&g_done, 1u);
        last = (n == 127u);
    }
    __syncthreads();
    if (last) {
        __threadfence();
        if (threadIdx.x < 128) {
            float v = __ldcg(&g_part[threadIdx.x]);
#pragma unroll
            for (int o = 16; o > 0; o >>= 1)
                v += __shfl_xor_sync(~0u, v, o);
            __shared__ float s[4];
            if ((threadIdx.x & 31) == 0) s[threadIdx.x >> 5] = v;
            __syncthreads();
            if (threadIdx.x == 0) {
                out[0] = (s[0] + s[1] + s[2] + s[3]) / (float)Bn;
                atomicExch(&g_done, 0u);
            }
        }
    }
}

extern "C" void kernel_launch(void* const* d_in, const int* in_sizes, int n_in,
                              void* d_out, int out_size) {
    const float* L = (const float*)d_in[0];
    float* out = (float*)d_out;
    k1_sums<<<P1, T1>>>(L);
    k2_finalize<<<128, 1024>>>(L, out);
}

// round 8
// speedup vs baseline: 1.4133x; 1.1283x over previous
#include <cuda_runtime.h>

#define Bn 4096
#define P1 296            // 148 SMs x 2 blocks
#define T1 512

// Scratch (fully rewritten every launch; g_done returns to 0 every launch)
__device__ float g_rs1[Bn];
__device__ float g_rs2[Bn];
__device__ float g_cp1[(size_t)P1 * Bn];   // 4.85 MB col partials of E
__device__ float g_cp2[(size_t)P1 * Bn];   // 4.85 MB col partials of E^2
__device__ float g_part[128];
__device__ unsigned g_done;

__device__ __forceinline__ float ex2f(float x) {
    float r; asm("ex2.approx.ftz.f32 %0, %1;" : "=f"(r) : "f"(x)); return r;
}
#define SCALE 2.8853900817779268f          // (1/t)/ln2, t = 0.5

// Pass 1: R4 streaming body, but the per-row reduction is 1 shfl + STS in
// the loop (short dependency chain) and a single deferred smem reduction at
// the end, instead of a 5-deep SHFL chain per row.
__global__ void __launch_bounds__(T1, 2) k1_sums(const float* __restrict__ L) {
    const int t = threadIdx.x;
    const int bid = blockIdx.x;
    const int warp = t >> 5, lane = t & 31;
    const int R = (bid < 248) ? 14 : 13;   // 248*14 + 48*13 = 4096

    float c1[8], c2[8];
#pragma unroll
    for (int j = 0; j < 8; j++) { c1[j] = 0.f; c2[j] = 0.f; }

    __shared__ float s1[14][256];          // 2-way-reduced row partials
    __shared__ float s2[14][256];          // (16 lanes x 16 warps per row)

    const int sidx = warp * 16 + (lane & 15);
    const bool lo16 = (lane < 16);

    int k = 0;
    for (; k + 2 <= R; k += 2) {
        const float4* __restrict__ rowA = (const float4*)(L + (size_t)(bid + k * P1) * Bn);
        const float4* __restrict__ rowB = (const float4*)(L + (size_t)(bid + (k + 1) * P1) * Bn);
        float4 a0 = __ldcs(rowA + t);
        float4 a1 = __ldcs(rowA + t + T1);
        float4 b0 = __ldcs(rowB + t);
        float4 b1 = __ldcs(rowB + t + T1);
        float xa[8] = {a0.x, a0.y, a0.z, a0.w, a1.x, a1.y, a1.z, a1.w};
        float xb[8] = {b0.x, b0.y, b0.z, b0.w, b1.x, b1.y, b1.z, b1.w};
        float ra1 = 0.f, ra2 = 0.f, rb1 = 0.f, rb2 = 0.f;
#pragma unroll
        for (int j = 0; j < 8; j++) {
            float ea = ex2f(xa[j] * SCALE);
            float eb = ex2f(xb[j] * SCALE);
            ra1 += ea;  rb1 += eb;
            c1[j] += ea + eb;
            ra2 = fmaf(ea, ea, ra2);
            rb2 = fmaf(eb, eb, rb2);
            c2[j] = fmaf(ea, ea, fmaf(eb, eb, c2[j]));
        }
        // single shuffle level, then park 2-way partials in smem
        ra1 += __shfl_xor_sync(~0u, ra1, 16);
        ra2 += __shfl_xor_sync(~0u, ra2, 16);
        rb1 += __shfl_xor_sync(~0u, rb1, 16);
        rb2 += __shfl_xor_sync(~0u, rb2, 16);
        if (lo16) {
            s1[k][sidx] = ra1;      s2[k][sidx] = ra2;
            s1[k + 1][sidx] = rb1;  s2[k + 1][sidx] = rb2;
        }
    }
    if (k < R) {  // tail row (R odd)
        const float4* __restrict__ row = (const float4*)(L + (size_t)(bid + k * P1) * Bn);
        float4 a0 = __ldcs(row + t);
        float4 a1 = __ldcs(row + t + T1);
        float x[8] = {a0.x, a0.y, a0.z, a0.w, a1.x, a1.y, a1.z, a1.w};
        float ra1 = 0.f, ra2 = 0.f;
#pragma unroll
        for (int j = 0; j < 8; j++) {
            float e = ex2f(x[j] * SCALE);
            ra1 += e; c1[j] += e;
            ra2 = fmaf(e, e, ra2);
            c2[j] = fmaf(e, e, c2[j]);
        }
        ra1 += __shfl_xor_sync(~0u, ra1, 16);
        ra2 += __shfl_xor_sync(~0u, ra2, 16);
        if (lo16) { s1[k][sidx] = ra1; s2[k][sidx] = ra2; }
    }
    __syncthreads();

    // Deferred row reduction: warp r reduces row r's 256 partials.
    if (warp < R) {
        float a = 0.f, b = 0.f;
#pragma unroll
        for (int i = 0; i < 8; i++) {
            a += s1[warp][lane + i * 32];
            b += s2[warp][lane + i * 32];
        }
#pragma unroll
        for (int o = 16; o > 0; o >>= 1) {
            a += __shfl_xor_sync(~0u, a, o);
            b += __shfl_xor_sync(~0u, b, o);
        }
        if (lane == 0) {
            g_rs1[bid + warp * P1] = a;
            g_rs2[bid + warp * P1] = b;
        }
    }

    float4* __restrict__ p1 = (float4*)(g_cp1 + (size_t)bid * Bn);
    float4* __restrict__ p2 = (float4*)(g_cp2 + (size_t)bid * Bn);
    p1[t]      = make_float4(c1[0], c1[1], c1[2], c1[3]);
    p1[t + T1] = make_float4(c1[4], c1[5], c1[6], c1[7]);
    p2[t]      = make_float4(c2[0], c2[1], c2[2], c2[3]);
    p2[t + T1] = make_float4(c2[4], c2[5], c2[6], c2[7]);
}

// Pass 2 (R4 best version): 128 blocks x 1024 threads, 32 cols x 32 stripe
// groups, smem tree, per-row loss, last-block fixed-order final mean.
__global__ void __launch_bounds__(1024) k2_finalize(const float* __restrict__ L,
                                                    float* __restrict__ out) {
    const int tx = threadIdx.x & 31;
    const int g  = threadIdx.x >> 5;
    const int col = blockIdx.x * 32 + tx;

    float a = 0.0f, b = 0.0f;
#pragma unroll 10
    for (int p = g; p < P1; p += 32) {
        a += g_cp1[(size_t)p * Bn + col];
        b += g_cp2[(size_t)p * Bn + col];
    }
    __shared__ float sa[32][33];
    __shared__ float sb[32][33];
    sa[g][tx] = a;  sb[g][tx] = b;
    __syncthreads();

    if (threadIdx.x < 32) {
        float ra = 0.0f, rb = 0.0f;
#pragma unroll
        for (int w = 0; w < 32; w++) { ra += sa[w][tx]; rb += sb[w][tx]; }
        const int i = col;
        const float Nf    = 8190.0f;                         // 2B-2
        const float minNg = 8190.0f * 0.13533528323661270f;  // N*exp(-1/t)
        float d  = L[(size_t)i * Bn + i];
        float e  = ex2f(d * SCALE);
        float e2 = e * e;
        float S1 = g_rs1[i] + ra - 2.0f * e;
        float S2 = g_rs2[i] + rb - 2.0f * e2;
        float Ng = (Nf * S2 / S1 - 0.1f * Nf * e) * (1.0f / 0.9f);
        Ng = fmaxf(Ng, minNg);
        float loss = logf((e + Ng + 1e-8f) / e);
#pragma unroll
        for (int o = 16; o > 0; o >>= 1)
            loss += __shfl_xor_sync(~0u, loss, o);
        if (tx == 0) g_part[blockIdx.x] = loss;
    }

    __shared__ bool last;
    if (threadIdx.x == 0) {
        __threadfence();
        unsigned n = atomicAdd(&g_done, 1u);
        last = (n == 127u);
    }
    __syncthreads();
    if (last) {
        __threadfence();
        if (threadIdx.x < 128) {
            float v = __ldcg(&g_part[threadIdx.x]);
#pragma unroll
            for (int o = 16; o > 0; o >>= 1)
                v += __shfl_xor_sync(~0u, v, o);
            __shared__ float s[4];
            if ((threadIdx.x & 31) == 0) s[threadIdx.x >> 5] = v;
            __syncthreads();
            if (threadIdx.x == 0) {
                out[0] = (s[0] + s[1] + s[2] + s[3]) / (float)Bn;
                atomicExch(&g_done, 0u);
            }
        }
    }
}

extern "C" void kernel_launch(void* const* d_in, const int* in_sizes, int n_in,
                              void* d_out, int out_size) {
    const float* L = (const float*)d_in[0];
    float* out = (float*)d_out;
    k1_sums<<<P1, T1>>>(L);
    k2_finalize<<<128, 1024>>>(L, out);
}

// round 9
// speedup vs baseline: 1.4324x; 1.0135x over previous
#include <cuda_runtime.h>

#define Bn 4096
#define P1 296            // 148 SMs x 2 blocks
#define T1 512

// Scratch (fully rewritten every launch; g_done returns to 0 every launch)
__device__ float g_rs1[Bn];
__device__ float g_rs2[Bn];
__device__ float g_cp1[(size_t)P1 * Bn];   // 4.85 MB col partials of E
__device__ float g_cp2[(size_t)P1 * Bn];   // 4.85 MB col partials of E^2
__device__ float g_part[128];
__device__ unsigned g_done;

__device__ __forceinline__ float ex2f(float x) {
    float r; asm("ex2.approx.ftz.f32 %0, %1;" : "=f"(r) : "f"(x)); return r;
}
#define SCALE 2.8853900817779268f          // (1/t)/ln2, t = 0.5

// Pass 1: best-known (R4) streaming body, untouched.
__global__ void __launch_bounds__(T1, 2) k1_sums(const float* __restrict__ L) {
    const int t = threadIdx.x;
    const int bid = blockIdx.x;
    const int warp = t >> 5, lane = t & 31;
    const int R = (bid < 248) ? 14 : 13;   // 248*14 + 48*13 = 4096

    float c1[8], c2[8];
#pragma unroll
    for (int j = 0; j < 8; j++) { c1[j] = 0.f; c2[j] = 0.f; }

    __shared__ float s1[16][14];
    __shared__ float s2[16][14];

    int k = 0;
    for (; k + 2 <= R; k += 2) {
        const float4* __restrict__ rowA = (const float4*)(L + (size_t)(bid + k * P1) * Bn);
        const float4* __restrict__ rowB = (const float4*)(L + (size_t)(bid + (k + 1) * P1) * Bn);
        float4 a0 = __ldcs(rowA + t);
        float4 a1 = __ldcs(rowA + t + T1);
        float4 b0 = __ldcs(rowB + t);
        float4 b1 = __ldcs(rowB + t + T1);
        float xa[8] = {a0.x, a0.y, a0.z, a0.w, a1.x, a1.y, a1.z, a1.w};
        float xb[8] = {b0.x, b0.y, b0.z, b0.w, b1.x, b1.y, b1.z, b1.w};
        float ra1 = 0.f, ra2 = 0.f, rb1 = 0.f, rb2 = 0.f;
#pragma unroll
        for (int j = 0; j < 8; j++) {
            float ea = ex2f(xa[j] * SCALE);
            float eb = ex2f(xb[j] * SCALE);
            ra1 += ea;  rb1 += eb;
            c1[j] += ea + eb;
            ra2 = fmaf(ea, ea, ra2);
            rb2 = fmaf(eb, eb, rb2);
            c2[j] = fmaf(ea, ea, fmaf(eb, eb, c2[j]));
        }
#pragma unroll
        for (int o = 16; o > 0; o >>= 1) {
            ra1 += __shfl_xor_sync(~0u, ra1, o);
            ra2 += __shfl_xor_sync(~0u, ra2, o);
            rb1 += __shfl_xor_sync(~0u, rb1, o);
            rb2 += __shfl_xor_sync(~0u, rb2, o);
        }
        if (lane == 0) {
            s1[warp][k] = ra1;      s2[warp][k] = ra2;
            s1[warp][k + 1] = rb1;  s2[warp][k + 1] = rb2;
        }
    }
    if (k < R) {
        const float4* __restrict__ row = (const float4*)(L + (size_t)(bid + k * P1) * Bn);
        float4 a0 = __ldcs(row + t);
        float4 a1 = __ldcs(row + t + T1);
        float x[8] = {a0.x, a0.y, a0.z, a0.w, a1.x, a1.y, a1.z, a1.w};
        float ra1 = 0.f, ra2 = 0.f;
#pragma unroll
        for (int j = 0; j < 8; j++) {
            float e = ex2f(x[j] * SCALE);
            ra1 += e; c1[j] += e;
            ra2 = fmaf(e, e, ra2);
            c2[j] = fmaf(e, e, c2[j]);
        }
#pragma unroll
        for (int o = 16; o > 0; o >>= 1) {
            ra1 += __shfl_xor_sync(~0u, ra1, o);
            ra2 += __shfl_xor_sync(~0u, ra2, o);
        }
        if (lane == 0) { s1[warp][k] = ra1; s2[warp][k] = ra2; }
    }
    __syncthreads();
    if (t < R) {
        float a = 0.f, b = 0.f;
#pragma unroll
        for (int w = 0; w < 16; w++) { a += s1[w][t]; b += s2[w][t]; }
        g_rs1[bid + t * P1] = a;
        g_rs2[bid + t * P1] = b;
    }
    float4* __restrict__ p1 = (float4*)(g_cp1 + (size_t)bid * Bn);
    float4* __restrict__ p2 = (float4*)(g_cp2 + (size_t)bid * Bn);
    p1[t]      = make_float4(c1[0], c1[1], c1[2], c1[3]);
    p1[t + T1] = make_float4(c1[4], c1[5], c1[6], c1[7]);
    p2[t]      = make_float4(c2[0], c2[1], c2[2], c2[3]);
    p2[t + T1] = make_float4(c2[4], c2[5], c2[6], c2[7]);
}

// Pass 2: high-MLP column reduce. 9 fully-unrolled batched loads per array
// (+1 predicated for g<8: 296 = 9*32 + 8), then sum; smem tree; per-row
// loss; last-block fixed-order final mean.
__global__ void __launch_bounds__(1024) k2_finalize(const float* __restrict__ L,
                                                    float* __restrict__ out) {
    const int tx = threadIdx.x & 31;
    const int g  = threadIdx.x >> 5;
    const int col = blockIdx.x * 32 + tx;

    float va[9], vb[9];
#pragma unroll
    for (int i = 0; i < 9; i++) {           // p = g + 32i  (max 287 < 296)
        va[i] = __ldcg(&g_cp1[(size_t)(g + 32 * i) * Bn + col]);
        vb[i] = __ldcg(&g_cp2[(size_t)(g + 32 * i) * Bn + col]);
    }
    float ea = 0.f, eb = 0.f;
    if (g < 8) {                            // p = g + 288 (288..295)
        ea = __ldcg(&g_cp1[(size_t)(g + 288) * Bn + col]);
        eb = __ldcg(&g_cp2[(size_t)(g + 288) * Bn + col]);
    }
    float a = ea, b = eb;
#pragma unroll
    for (int i = 0; i < 9; i++) { a += va[i]; b += vb[i]; }

    __shared__ float sa[32][33];
    __shared__ float sb[32][33];
    sa[g][tx] = a;  sb[g][tx] = b;
    __syncthreads();

    if (threadIdx.x < 32) {
        float ra = 0.0f, rb = 0.0f;
#pragma unroll
        for (int w = 0; w < 32; w++) { ra += sa[w][tx]; rb += sb[w][tx]; }
        const int i = col;
        const float Nf    = 8190.0f;                         // 2B-2
        const float minNg = 8190.0f * 0.13533528323661270f;  // N*exp(-1/t)
        float d  = L[(size_t)i * Bn + i];
        float e  = ex2f(d * SCALE);
        float e2 = e * e;
        float S1 = g_rs1[i] + ra - 2.0f * e;
        float S2 = g_rs2[i] + rb - 2.0f * e2;
        float Ng = (Nf * S2 / S1 - 0.1f * Nf * e) * (1.0f / 0.9f);
        Ng = fmaxf(Ng, minNg);
        float loss = logf((e + Ng + 1e-8f) / e);
#pragma unroll
        for (int o = 16; o > 0; o >>= 1)
            loss += __shfl_xor_sync(~0u, loss, o);
        if (tx == 0) g_part[blockIdx.x] = loss;
    }

    __shared__ bool last;
    if (threadIdx.x == 0) {
        __threadfence();
        unsigned n = atomicAdd(&g_done, 1u);
        last = (n == 127u);
    }
    __syncthreads();
    if (last) {
        __threadfence();
        if (threadIdx.x < 128) {
            float v = __ldcg(&g_part[threadIdx.x]);
#pragma unroll
            for (int o = 16; o > 0; o >>= 1)
                v += __shfl_xor_sync(~0u, v, o);
            __shared__ float s[4];
            if ((threadIdx.x & 31) == 0) s[threadIdx.x >> 5] = v;
            __syncthreads();
            if (threadIdx.x == 0) {
                out[0] = (s[0] + s[1] + s[2] + s[3]) / (float)Bn;
                atomicExch(&g_done, 0u);
            }
        }
    }
}

// Observability shim: with 5 launches per replay, ncu's "-s 5 -c 1" capture
// lands on k1_sums instead of always k2. Removed once k1 is characterized.
__global__ void dummy_k() {}

extern "C" void kernel_launch(void* const* d_in, const int* in_sizes, int n_in,
                              void* d_out, int out_size) {
    const float* L = (const float*)d_in[0];
    float* out = (float*)d_out;
    k1_sums<<<P1, T1>>>(L);
    k2_finalize<<<128, 1024>>>(L, out);
    dummy_k<<<1, 32>>>();
    dummy_k<<<1, 32>>>();
    dummy_k<<<1, 32>>>();
}